// round 5
// baseline (speedup 1.0000x reference)
#include <cuda_runtime.h>
#include <cstdint>
#include <cstddef>

#define BB   4
#define NN   1024
#define DIMC 1024
#define HH   16
#define DHD  64

// Scratch (no cudaMalloc allowed)
__device__ float g_Q[(size_t)BB * NN * DIMC];
__device__ float g_K[(size_t)BB * NN * DIMC];
__device__ float g_V[(size_t)BB * NN * DIMC];
__device__ float g_O[(size_t)BB * NN * DIMC];
__device__ float g_Xr[(size_t)BB * NN * DIMC];
__device__ float g_Wqr[(size_t)DIMC * HH * DHD];
__device__ float g_Wkr[(size_t)DIMC * HH * DHD];
__device__ float g_Wvr[(size_t)DIMC * HH * DHD];
__device__ float g_Wor[(size_t)HH * DHD * DIMC];

__device__ __forceinline__ float tf32r(float x) {
    uint32_t u;
    asm("cvt.rna.tf32.f32 %0, %1;" : "=r"(u) : "f"(x));
    return __uint_as_float(u);
}

__device__ __forceinline__ void cp16(float* smem, const float* gmem) {
    uint32_t s = (uint32_t)__cvta_generic_to_shared(smem);
    asm volatile("cp.async.cg.shared.global [%0], [%1], 16;" :: "r"(s), "l"(gmem));
}
__device__ __forceinline__ void cp_commit() { asm volatile("cp.async.commit_group;"); }
__device__ __forceinline__ void cp_wait1()  { asm volatile("cp.async.wait_group 1;"); }
__device__ __forceinline__ void cp_wait2()  { asm volatile("cp.async.wait_group 2;"); }

#define MMA_TF32(d, a0, a1, a2, a3, b0, b1)                                 \
    asm volatile(                                                           \
        "mma.sync.aligned.m16n8k8.row.col.f32.tf32.tf32.f32 "               \
        "{%0,%1,%2,%3}, {%4,%5,%6,%7}, {%8,%9}, {%0,%1,%2,%3};"             \
        : "+f"(d[0]), "+f"(d[1]), "+f"(d[2]), "+f"(d[3])                    \
        : "r"(a0), "r"(a1), "r"(a2), "r"(a3), "r"(b0), "r"(b1))

// ---------------------------------------------------------------------------
// Pre-round x and all weights to tf32 (rna) once.
// ---------------------------------------------------------------------------
__global__ __launch_bounds__(256) void round_all(
    const float* __restrict__ x,
    const float* __restrict__ Wq, const float* __restrict__ Wk,
    const float* __restrict__ Wv, const float* __restrict__ Wo,
    float* __restrict__ xr,
    float* __restrict__ wqr, float* __restrict__ wkr,
    float* __restrict__ wvr, float* __restrict__ wor)
{
    int i = blockIdx.x * blockDim.x + threadIdx.x;   // float4 index, 2M total
    const float* src; float* dst; int off;
    if (i < (1 << 20)) { src = x; dst = xr; off = i; }
    else {
        int j = i - (1 << 20);
        int w = j >> 18; off = j & ((1 << 18) - 1);
        src = (w == 0) ? Wq : (w == 1) ? Wk : (w == 2) ? Wv : Wo;
        dst = (w == 0) ? wqr : (w == 1) ? wkr : (w == 2) ? wvr : wor;
    }
    float4 v = ((const float4*)src)[off];
    v.x = tf32r(v.x); v.y = tf32r(v.y); v.z = tf32r(v.z); v.w = tf32r(v.w);
    ((float4*)dst)[off] = v;
}

// ---------------------------------------------------------------------------
// tf32 GEMM with 3-stage cp.async pipeline. Inputs pre-rounded.
// C = A[M,K] @ B[K,Nc]; 128x128 block, BK=16, 256 threads (8 warps 2m x 4n).
// As[m][k] stride 20 (conflict-free reads+writes), Bs stride 136 + XOR swizzle.
// ROUND_OUT: store tf32r(acc*outScale); else store acc + bias.
// ---------------------------------------------------------------------------
#define GEMM_SMEM ((3 * 128 * 20 + 3 * 16 * 136) * 4)   // 56832 B

template<bool ROUND_OUT>
__device__ __forceinline__ void gemm_body(
    const float* __restrict__ A, const float* __restrict__ Bm,
    float* __restrict__ C, const float* __restrict__ bias,
    float outScale, int M, int K, int Nc)
{
    extern __shared__ float smg[];
    float* As = smg;                    // [3][128][20]
    float* Bs = smg + 3 * 128 * 20;     // [3][16][136]

    const int t     = threadIdx.x;
    const int wid   = t >> 5, lane = t & 31;
    const int group = lane >> 2, tig = lane & 3;
    const int wm    = (wid & 1) * 64;
    const int wn    = (wid >> 1) * 32;
    const int m0    = blockIdx.y * 128;
    const int n0    = blockIdx.x * 128;

    auto load_stage = [&](int s, int k0) {
        float* Ad = As + s * 2560;
        float* Bd = Bs + s * 2176;
        #pragma unroll
        for (int l = 0; l < 2; l++) {
            int c = l * 256 + t;
            int r = c >> 2, k4 = (c & 3) * 4;
            cp16(Ad + r * 20 + k4, A + (size_t)(m0 + r) * K + k0 + k4);
            int kr = c >> 5, b4 = (c & 31) * 4;
            cp16(Bd + kr * 136 + (b4 ^ ((kr & 12) << 1)),
                 Bm + (size_t)(k0 + kr) * Nc + n0 + b4);
        }
    };

    float acc[4][4][4] = {};

    load_stage(0, 0);  cp_commit();
    load_stage(1, 16); cp_commit();

    int s = 0;
    for (int k0 = 0; k0 < K; k0 += 16) {
        cp_wait1();
        __syncthreads();
        int s2 = (s >= 1) ? s - 1 : s + 2;
        if (k0 + 32 < K) load_stage(s2, k0 + 32);
        cp_commit();

        const float* Ac = As + s * 2560;
        const float* Bc = Bs + s * 2176;
        #pragma unroll
        for (int ks = 0; ks < 2; ks++) {
            int kk = ks * 8;
            int s0 = kk << 1;
            int s1 = ((kk + 4) & 12) << 1;
            uint32_t a[4][4];
            #pragma unroll
            for (int mf = 0; mf < 4; mf++) {
                int mb = wm + mf * 16;
                a[mf][0] = __float_as_uint(Ac[(mb + group    ) * 20 + kk + tig    ]);
                a[mf][1] = __float_as_uint(Ac[(mb + group + 8) * 20 + kk + tig    ]);
                a[mf][2] = __float_as_uint(Ac[(mb + group    ) * 20 + kk + tig + 4]);
                a[mf][3] = __float_as_uint(Ac[(mb + group + 8) * 20 + kk + tig + 4]);
            }
            #pragma unroll
            for (int nf = 0; nf < 4; nf++) {
                int nb = wn + nf * 8;
                uint32_t b0 = __float_as_uint(Bc[(kk + tig    ) * 136 + ((nb + group) ^ s0)]);
                uint32_t b1 = __float_as_uint(Bc[(kk + tig + 4) * 136 + ((nb + group) ^ s1)]);
                #pragma unroll
                for (int mf = 0; mf < 4; mf++)
                    MMA_TF32(acc[mf][nf], a[mf][0], a[mf][1], a[mf][2], a[mf][3], b0, b1);
            }
        }
        s = (s == 2) ? 0 : s + 1;
        __syncthreads();
    }

    #pragma unroll
    for (int mf = 0; mf < 4; mf++) {
        #pragma unroll
        for (int nf = 0; nf < 4; nf++) {
            int row = m0 + wm + mf * 16 + group;
            int col = n0 + wn + nf * 8 + tig * 2;
            float v0, v1, v2, v3;
            if (ROUND_OUT) {
                v0 = tf32r(acc[mf][nf][0] * outScale);
                v1 = tf32r(acc[mf][nf][1] * outScale);
                v2 = tf32r(acc[mf][nf][2] * outScale);
                v3 = tf32r(acc[mf][nf][3] * outScale);
            } else {
                float bx = bias[col], by = bias[col + 1];
                v0 = acc[mf][nf][0] + bx; v1 = acc[mf][nf][1] + by;
                v2 = acc[mf][nf][2] + bx; v3 = acc[mf][nf][3] + by;
            }
            *(float2*)(C + (size_t)row       * Nc + col) = make_float2(v0, v1);
            *(float2*)(C + (size_t)(row + 8) * Nc + col) = make_float2(v2, v3);
        }
    }
}

__global__ __launch_bounds__(256, 2) void gemm_qkv(
    const float* __restrict__ x,
    const float* __restrict__ Wq, const float* __restrict__ Wk,
    const float* __restrict__ Wv,
    float* __restrict__ Qo, float* __restrict__ Ko, float* __restrict__ Vo)
{
    const float* W = (blockIdx.z == 0) ? Wq : (blockIdx.z == 1) ? Wk : Wv;
    float*       C = (blockIdx.z == 0) ? Qo : (blockIdx.z == 1) ? Ko : Vo;
    float scale    = (blockIdx.z == 0) ? 0.125f : 1.0f;
    gemm_body<true>(x, W, C, nullptr, scale, BB * NN, DIMC, HH * DHD);
}

__global__ __launch_bounds__(256, 2) void gemm_out(
    const float* __restrict__ A, const float* __restrict__ W,
    float* __restrict__ C, const float* __restrict__ bias)
{
    gemm_body<false>(A, W, C, bias, 1.0f, BB * NN, DIMC, DIMC);
}

// ---------------------------------------------------------------------------
// attn_qk: per (b, h, 32 q-rows): S = Qs @ K^T (Q pre-scaled+rounded),
// softmax, normalized attn store. 512 threads. cp.async staging:
// Q one-shot, K double-buffered 128-row chunks.
// ---------------------------------------------------------------------------
#define SP  1028
#define KST 68
#define ATTN_SMEM ((32 * SP + 32 * KST + 2 * 128 * KST) * 4)   // 209920 B

__global__ __launch_bounds__(512, 1) void attn_qk(
    const float* __restrict__ Q, const float* __restrict__ Kt,
    float* __restrict__ attn)
{
    extern __shared__ float sm[];
    float* S  = sm;                   // [32][SP]
    float* Tq = S + 32 * SP;          // [32][KST]
    float* Tk = Tq + 32 * KST;        // [2][128][KST]
    __shared__ float sinv[32];

    const int t     = threadIdx.x;
    const int wid   = t >> 5, lane = t & 31;
    const int group = lane >> 2, tig = lane & 3;
    const int iq0   = blockIdx.x * 32;
    const int h     = blockIdx.y, b = blockIdx.z;
    const size_t base = (size_t)b * NN * DIMC + (size_t)h * DHD;

    auto loadK = [&](int buf, int c) {
        float* Td = Tk + buf * 128 * KST;
        #pragma unroll
        for (int p = 0; p < 4; p++) {
            int i = p * 512 + t;
            int j = i >> 4, d4 = (i & 15) * 4;
            cp16(Td + j * KST + d4, Kt + base + (size_t)(c * 128 + j) * DIMC + d4);
        }
    };

    // Q (pre-scaled, pre-rounded): one cp.async group
    {
        int r = t >> 4, d4 = (t & 15) * 4;
        cp16(Tq + r * KST + d4, Q + base + (size_t)(iq0 + r) * DIMC + d4);
    }
    cp_commit();
    loadK(0, 0); cp_commit();
    loadK(1, 1); cp_commit();

    cp_wait2();          // Q ready
    __syncthreads();

    const int wmq = (wid & 1) * 16;
    const int wnq = (wid >> 1) * 16;

    uint32_t qa[8][4];
    #pragma unroll
    for (int ks = 0; ks < 8; ks++) {
        int kk = ks * 8;
        qa[ks][0] = __float_as_uint(Tq[(wmq + group    ) * KST + kk + tig    ]);
        qa[ks][1] = __float_as_uint(Tq[(wmq + group + 8) * KST + kk + tig    ]);
        qa[ks][2] = __float_as_uint(Tq[(wmq + group    ) * KST + kk + tig + 4]);
        qa[ks][3] = __float_as_uint(Tq[(wmq + group + 8) * KST + kk + tig + 4]);
    }

    for (int c = 0; c < 8; c++) {
        cp_wait1();          // K chunk c resident
        __syncthreads();

        const float* Tc = Tk + (c & 1) * 128 * KST;
        float acc[2][4] = {};
        #pragma unroll
        for (int ks = 0; ks < 8; ks++) {
            int kk = ks * 8;
            #pragma unroll
            for (int nf = 0; nf < 2; nf++) {
                int nb = wnq + nf * 8;
                uint32_t b0 = __float_as_uint(Tc[(nb + group) * KST + kk + tig    ]);
                uint32_t b1 = __float_as_uint(Tc[(nb + group) * KST + kk + tig + 4]);
                MMA_TF32(acc[nf], qa[ks][0], qa[ks][1], qa[ks][2], qa[ks][3], b0, b1);
            }
        }
        #pragma unroll
        for (int nf = 0; nf < 2; nf++) {
            int col = c * 128 + wnq + nf * 8 + tig * 2;
            *(float2*)(S + (size_t)(wmq + group    ) * SP + col) = make_float2(acc[nf][0], acc[nf][1]);
            *(float2*)(S + (size_t)(wmq + group + 8) * SP + col) = make_float2(acc[nf][2], acc[nf][3]);
        }
        __syncthreads();     // all warps done with buf (c&1) before refill
        if (c < 6) loadK(c & 1, c + 2);
        cp_commit();
    }

    // softmax
    {
        int r = t >> 4, g = t & 15;
        float* row = S + (size_t)r * SP;
        float m = -1e30f;
        #pragma unroll
        for (int p = 0; p < 16; p++) {
            float4 v = *(const float4*)(row + (p * 16 + g) * 4);
            m = fmaxf(m, fmaxf(fmaxf(v.x, v.y), fmaxf(v.z, v.w)));
        }
        #pragma unroll
        for (int o = 8; o; o >>= 1) m = fmaxf(m, __shfl_xor_sync(0xffffffffu, m, o, 16));
        float s = 0.f;
        #pragma unroll
        for (int p = 0; p < 16; p++) {
            float4 v = *(float4*)(row + (p * 16 + g) * 4);
            v.x = __expf(v.x - m); v.y = __expf(v.y - m);
            v.z = __expf(v.z - m); v.w = __expf(v.w - m);
            s += v.x + v.y + v.z + v.w;
            *(float4*)(row + (p * 16 + g) * 4) = v;
        }
        #pragma unroll
        for (int o = 8; o; o >>= 1) s += __shfl_xor_sync(0xffffffffu, s, o, 16);
        if (g == 0) sinv[r] = 1.f / s;
    }
    __syncthreads();

    // normalized attn store (coalesced float4)
    {
        const size_t abase = (((size_t)b * HH + h) * NN + iq0) * NN;
        #pragma unroll
        for (int p = 0; p < 16; p++) {
            int r  = p * 2 + (t >> 8);
            int c4 = (t & 255) * 4;
            float inv = sinv[r];
            float4 v = *(const float4*)(S + (size_t)r * SP + c4);
            v.x *= inv; v.y *= inv; v.z *= inv; v.w *= inv;
            *(float4*)(attn + abase + (size_t)r * NN + c4) = v;
        }
    }
}

// ---------------------------------------------------------------------------
// pv_gemm: O = attn @ V per (mtile, h, b). 256m x 64n, BK=16, 3-stage
// cp.async. P staged raw, tf32-rounded at fragment read; V pre-rounded.
// Output stored tf32-rounded (feeds gemm_out raw).
// ---------------------------------------------------------------------------
#define PV_SMEM ((3 * 256 * 20 + 3 * 16 * 72) * 4)   // 75264 B

__global__ __launch_bounds__(256, 2) void pv_gemm(
    const float* __restrict__ P, const float* __restrict__ V,
    float* __restrict__ O)
{
    extern __shared__ float smp[];
    float* As = smp;                    // [3][256][20]
    float* Bs = smp + 3 * 256 * 20;     // [3][16][72]

    const int t     = threadIdx.x;
    const int wid   = t >> 5, lane = t & 31;
    const int group = lane >> 2, tig = lane & 3;
    const int wm    = (wid & 3) * 64;
    const int wn    = (wid >> 2) * 32;
    const int m0    = blockIdx.x * 256;
    const int h     = blockIdx.y, b = blockIdx.z;

    const float* Pb = P + (((size_t)b * HH + h) * NN + m0) * NN;
    const float* Vb = V + (size_t)b * NN * DIMC + (size_t)h * DHD;
    float*       Ob = O + (size_t)b * NN * DIMC + (size_t)h * DHD;

    auto load_stage = [&](int s, int k0) {
        float* Ad = As + s * 5120;
        float* Bd = Bs + s * 1152;
        #pragma unroll
        for (int l = 0; l < 4; l++) {
            int c = l * 256 + t;
            int r = c >> 2, k4 = (c & 3) * 4;
            cp16(Ad + r * 20 + k4, Pb + (size_t)r * NN + k0 + k4);
        }
        {
            int kr = t >> 4, n4 = (t & 15) * 4;
            cp16(Bd + kr * 72 + n4, Vb + (size_t)(k0 + kr) * DIMC + n4);
        }
    };

    float acc[4][4][4] = {};

    load_stage(0, 0);  cp_commit();
    load_stage(1, 16); cp_commit();

    int s = 0;
    for (int k0 = 0; k0 < NN; k0 += 16) {
        cp_wait1();
        __syncthreads();
        int s2 = (s >= 1) ? s - 1 : s + 2;
        if (k0 + 32 < NN) load_stage(s2, k0 + 32);
        cp_commit();

        const float* Ac = As + s * 5120;
        const float* Bc = Bs + s * 1152;
        #pragma unroll
        for (int ks = 0; ks < 2; ks++) {
            int kk = ks * 8;
            uint32_t a[4][4];
            #pragma unroll
            for (int mf = 0; mf < 4; mf++) {
                int mb = wm + mf * 16;
                a[mf][0] = __float_as_uint(tf32r(Ac[(mb + group    ) * 20 + kk + tig    ]));
                a[mf][1] = __float_as_uint(tf32r(Ac[(mb + group + 8) * 20 + kk + tig    ]));
                a[mf][2] = __float_as_uint(tf32r(Ac[(mb + group    ) * 20 + kk + tig + 4]));
                a[mf][3] = __float_as_uint(tf32r(Ac[(mb + group + 8) * 20 + kk + tig + 4]));
            }
            #pragma unroll
            for (int nf = 0; nf < 4; nf++) {
                int nb = wn + nf * 8;
                uint32_t b0 = __float_as_uint(Bc[(kk + tig    ) * 72 + nb + group]);
                uint32_t b1 = __float_as_uint(Bc[(kk + tig + 4) * 72 + nb + group]);
                #pragma unroll
                for (int mf = 0; mf < 4; mf++)
                    MMA_TF32(acc[mf][nf], a[mf][0], a[mf][1], a[mf][2], a[mf][3], b0, b1);
            }
        }
        s = (s == 2) ? 0 : s + 1;
        __syncthreads();
    }

    #pragma unroll
    for (int mf = 0; mf < 4; mf++) {
        #pragma unroll
        for (int nf = 0; nf < 4; nf++) {
            int row = m0 + wm + mf * 16 + group;
            int col = wn + nf * 8 + tig * 2;
            *(float2*)(Ob + (size_t)row       * DIMC + col) =
                make_float2(tf32r(acc[mf][nf][0]), tf32r(acc[mf][nf][1]));
            *(float2*)(Ob + (size_t)(row + 8) * DIMC + col) =
                make_float2(tf32r(acc[mf][nf][2]), tf32r(acc[mf][nf][3]));
        }
    }
}

// ---------------------------------------------------------------------------
extern "C" void kernel_launch(void* const* d_in, const int* in_sizes, int n_in,
                              void* d_out, int out_size)
{
    const float* x  = (const float*)d_in[0];
    const float* Wq = (const float*)d_in[1];
    const float* Wk = (const float*)d_in[2];
    const float* Wv = (const float*)d_in[3];
    const float* Wo = (const float*)d_in[4];
    const float* bo = (const float*)d_in[5];

    float* out  = (float*)d_out;
    float* attn = out + (size_t)BB * NN * DIMC;

    float *Qp, *Kp, *Vp, *Op, *Xr, *Wqr, *Wkr, *Wvr, *Wor;
    cudaGetSymbolAddress((void**)&Qp,  g_Q);
    cudaGetSymbolAddress((void**)&Kp,  g_K);
    cudaGetSymbolAddress((void**)&Vp,  g_V);
    cudaGetSymbolAddress((void**)&Op,  g_O);
    cudaGetSymbolAddress((void**)&Xr,  g_Xr);
    cudaGetSymbolAddress((void**)&Wqr, g_Wqr);
    cudaGetSymbolAddress((void**)&Wkr, g_Wkr);
    cudaGetSymbolAddress((void**)&Wvr, g_Wvr);
    cudaGetSymbolAddress((void**)&Wor, g_Wor);

    cudaFuncSetAttribute(gemm_qkv, cudaFuncAttributeMaxDynamicSharedMemorySize, GEMM_SMEM);
    cudaFuncSetAttribute(gemm_out, cudaFuncAttributeMaxDynamicSharedMemorySize, GEMM_SMEM);
    cudaFuncSetAttribute(attn_qk,  cudaFuncAttributeMaxDynamicSharedMemorySize, ATTN_SMEM);
    cudaFuncSetAttribute(pv_gemm,  cudaFuncAttributeMaxDynamicSharedMemorySize, PV_SMEM);

    round_all<<<8192, 256>>>(x, Wq, Wk, Wv, Wo, Xr, Wqr, Wkr, Wvr, Wor);

    dim3 gQKV(8, 32, 3);
    gemm_qkv<<<gQKV, 256, GEMM_SMEM>>>(Xr, Wqr, Wkr, Wvr, Qp, Kp, Vp);

    dim3 gQK(NN / 32, HH, BB);
    attn_qk<<<gQK, 512, ATTN_SMEM>>>(Qp, Kp, attn);

    dim3 gPV(NN / 256, HH, BB);
    pv_gemm<<<gPV, 256, PV_SMEM>>>(attn, Vp, Op);

    dim3 gOut(8, 32);
    gemm_out<<<gOut, 256, GEMM_SMEM>>>(Op, Wor, out, bo);
}

// round 6
// speedup vs baseline: 1.5355x; 1.5355x over previous
#include <cuda_runtime.h>
#include <cstdint>
#include <cstddef>

#define BB   4
#define NN   1024
#define DIMC 1024
#define HH   16
#define DHD  64

// Scratch (no cudaMalloc allowed)
__device__ float g_Q[(size_t)BB * NN * DIMC];
__device__ float g_K[(size_t)BB * NN * DIMC];
__device__ float g_V[(size_t)BB * NN * DIMC];
__device__ float g_O[(size_t)BB * NN * DIMC];
__device__ float g_Xr[(size_t)BB * NN * DIMC];
__device__ float g_Wqr[(size_t)DIMC * HH * DHD];
__device__ float g_Wkr[(size_t)DIMC * HH * DHD];
__device__ float g_Wvr[(size_t)DIMC * HH * DHD];
__device__ float g_Wor[(size_t)HH * DHD * DIMC];

__device__ __forceinline__ float tf32r(float x) {
    uint32_t u;
    asm("cvt.rna.tf32.f32 %0, %1;" : "=r"(u) : "f"(x));
    return __uint_as_float(u);
}

__device__ __forceinline__ void cp16(float* smem, const float* gmem) {
    uint32_t s = (uint32_t)__cvta_generic_to_shared(smem);
    asm volatile("cp.async.cg.shared.global [%0], [%1], 16;" :: "r"(s), "l"(gmem));
}
__device__ __forceinline__ void cp_commit() { asm volatile("cp.async.commit_group;"); }
__device__ __forceinline__ void cp_wait1()  { asm volatile("cp.async.wait_group 1;"); }

#define MMA_TF32(d, a0, a1, a2, a3, b0, b1)                                 \
    asm volatile(                                                           \
        "mma.sync.aligned.m16n8k8.row.col.f32.tf32.tf32.f32 "               \
        "{%0,%1,%2,%3}, {%4,%5,%6,%7}, {%8,%9}, {%0,%1,%2,%3};"             \
        : "+f"(d[0]), "+f"(d[1]), "+f"(d[2]), "+f"(d[3])                    \
        : "r"(a0), "r"(a1), "r"(a2), "r"(a3), "r"(b0), "r"(b1))

// ---------------------------------------------------------------------------
// Pre-round x and all weights to tf32 (rna) once.
// ---------------------------------------------------------------------------
__global__ __launch_bounds__(256) void round_all(
    const float* __restrict__ x,
    const float* __restrict__ Wq, const float* __restrict__ Wk,
    const float* __restrict__ Wv, const float* __restrict__ Wo,
    float* __restrict__ xr,
    float* __restrict__ wqr, float* __restrict__ wkr,
    float* __restrict__ wvr, float* __restrict__ wor)
{
    int i = blockIdx.x * blockDim.x + threadIdx.x;   // float4 index, 2M total
    const float* src; float* dst; int off;
    if (i < (1 << 20)) { src = x; dst = xr; off = i; }
    else {
        int j = i - (1 << 20);
        int w = j >> 18; off = j & ((1 << 18) - 1);
        src = (w == 0) ? Wq : (w == 1) ? Wk : (w == 2) ? Wv : Wo;
        dst = (w == 0) ? wqr : (w == 1) ? wkr : (w == 2) ? wvr : wor;
    }
    float4 v = ((const float4*)src)[off];
    v.x = tf32r(v.x); v.y = tf32r(v.y); v.z = tf32r(v.z); v.w = tf32r(v.w);
    ((float4*)dst)[off] = v;
}

// ---------------------------------------------------------------------------
// tf32 GEMM, 512 threads, 128x128 tile, BK=16, 3-stage cp.async pipeline.
// 16 warps (4m x 4n), warp tile 32x32 -> 32 acc regs/thread.
// As[m][k] stride 20, Bs[k][n] stride 136 + XOR swizzle (both conflict-free).
// Inputs pre-rounded to tf32. ROUND_OUT: store tf32r(acc*outScale).
// ---------------------------------------------------------------------------
#define GEMM_SMEM ((3 * 128 * 20 + 3 * 16 * 136) * 4)   // 56832 B

template<bool ROUND_OUT>
__device__ __forceinline__ void gemm_body(
    const float* __restrict__ A, const float* __restrict__ Bm,
    float* __restrict__ C, const float* __restrict__ bias,
    float outScale, int K, int Nc)
{
    extern __shared__ float smg[];
    float* As = smg;                    // [3][128][20]
    float* Bs = smg + 3 * 2560;         // [3][16][136]

    const int t     = threadIdx.x;
    const int wid   = t >> 5, lane = t & 31;
    const int group = lane >> 2, tig = lane & 3;
    const int wm    = (wid & 3) * 32;
    const int wn    = (wid >> 2) * 32;
    const int m0    = blockIdx.y * 128;
    const int n0    = blockIdx.x * 128;

    auto load_stage = [&](int s, int k0) {
        float* Ad = As + s * 2560;
        float* Bd = Bs + s * 2176;
        {   // A: 128x16, one cp16 per thread
            int r = t >> 2, k4 = (t & 3) * 4;
            cp16(Ad + r * 20 + k4, A + (size_t)(m0 + r) * K + k0 + k4);
        }
        {   // B: 16x128, one cp16 per thread
            int kr = t >> 5, b4 = (t & 31) * 4;
            cp16(Bd + kr * 136 + (b4 ^ ((kr & 12) << 1)),
                 Bm + (size_t)(k0 + kr) * Nc + n0 + b4);
        }
    };

    float acc[2][4][4] = {};

    load_stage(0, 0);  cp_commit();
    load_stage(1, 16); cp_commit();

    int s = 0;
    for (int k0 = 0; k0 < K; k0 += 16) {
        cp_wait1();
        __syncthreads();
        int s2 = (s >= 1) ? s - 1 : s + 2;
        if (k0 + 32 < K) load_stage(s2, k0 + 32);
        cp_commit();

        const float* Ac = As + s * 2560;
        const float* Bc = Bs + s * 2176;
        #pragma unroll
        for (int ks = 0; ks < 2; ks++) {
            int kk = ks * 8;
            int s0 = kk << 1;
            int s1 = ((kk + 4) & 12) << 1;
            uint32_t a[2][4];
            #pragma unroll
            for (int mf = 0; mf < 2; mf++) {
                int mb = wm + mf * 16;
                a[mf][0] = __float_as_uint(Ac[(mb + group    ) * 20 + kk + tig    ]);
                a[mf][1] = __float_as_uint(Ac[(mb + group + 8) * 20 + kk + tig    ]);
                a[mf][2] = __float_as_uint(Ac[(mb + group    ) * 20 + kk + tig + 4]);
                a[mf][3] = __float_as_uint(Ac[(mb + group + 8) * 20 + kk + tig + 4]);
            }
            #pragma unroll
            for (int nf = 0; nf < 4; nf++) {
                int nb = wn + nf * 8;
                uint32_t b0 = __float_as_uint(Bc[(kk + tig    ) * 136 + ((nb + group) ^ s0)]);
                uint32_t b1 = __float_as_uint(Bc[(kk + tig + 4) * 136 + ((nb + group) ^ s1)]);
                #pragma unroll
                for (int mf = 0; mf < 2; mf++)
                    MMA_TF32(acc[mf][nf], a[mf][0], a[mf][1], a[mf][2], a[mf][3], b0, b1);
            }
        }
        s = (s == 2) ? 0 : s + 1;
        __syncthreads();
    }

    #pragma unroll
    for (int mf = 0; mf < 2; mf++) {
        #pragma unroll
        for (int nf = 0; nf < 4; nf++) {
            int row = m0 + wm + mf * 16 + group;
            int col = n0 + wn + nf * 8 + tig * 2;
            float v0, v1, v2, v3;
            if (ROUND_OUT) {
                v0 = tf32r(acc[mf][nf][0] * outScale);
                v1 = tf32r(acc[mf][nf][1] * outScale);
                v2 = tf32r(acc[mf][nf][2] * outScale);
                v3 = tf32r(acc[mf][nf][3] * outScale);
            } else {
                float bx = bias[col], by = bias[col + 1];
                v0 = acc[mf][nf][0] + bx; v1 = acc[mf][nf][1] + by;
                v2 = acc[mf][nf][2] + bx; v3 = acc[mf][nf][3] + by;
            }
            *(float2*)(C + (size_t)row       * Nc + col) = make_float2(v0, v1);
            *(float2*)(C + (size_t)(row + 8) * Nc + col) = make_float2(v2, v3);
        }
    }
}

__global__ __launch_bounds__(512) void gemm_qkv(
    const float* __restrict__ x,
    const float* __restrict__ Wq, const float* __restrict__ Wk,
    const float* __restrict__ Wv,
    float* __restrict__ Qo, float* __restrict__ Ko, float* __restrict__ Vo)
{
    const float* W = (blockIdx.z == 0) ? Wq : (blockIdx.z == 1) ? Wk : Wv;
    float*       C = (blockIdx.z == 0) ? Qo : (blockIdx.z == 1) ? Ko : Vo;
    float scale    = (blockIdx.z == 0) ? 0.125f : 1.0f;
    gemm_body<true>(x, W, C, nullptr, scale, DIMC, HH * DHD);
}

__global__ __launch_bounds__(512) void gemm_out(
    const float* __restrict__ A, const float* __restrict__ W,
    float* __restrict__ C, const float* __restrict__ bias)
{
    gemm_body<false>(A, W, C, bias, 1.0f, DIMC, DIMC);
}

// ---------------------------------------------------------------------------
// attn_qk: per (b, h, 32 q-rows): S = Qs @ K^T (inputs pre-rounded, Q
// pre-scaled), softmax, normalized attn store. 512 threads, register-
// prefetched K chunks (R4-proven structure, staging cvt removed).
// ---------------------------------------------------------------------------
#define SP  1028
#define KST 68
#define ATTN_SMEM ((32 * SP + 128 * KST) * 4)   // 166400 B

__global__ __launch_bounds__(512, 1) void attn_qk(
    const float* __restrict__ Q, const float* __restrict__ Kt,
    float* __restrict__ attn)
{
    extern __shared__ float sm[];
    float* S = sm;               // [32][SP]
    float* T = sm + 32 * SP;     // [128][KST]
    __shared__ float sinv[32];

    const int t     = threadIdx.x;
    const int wid   = t >> 5, lane = t & 31;
    const int group = lane >> 2, tig = lane & 3;
    const int iq0   = blockIdx.x * 32;
    const int h     = blockIdx.y, b = blockIdx.z;
    const size_t base = (size_t)b * NN * DIMC + (size_t)h * DHD;

    // stage Q (already scaled+rounded)
    {
        int r = t >> 4, d4 = (t & 15) * 4;
        float4 v = *(const float4*)(Q + base + (size_t)(iq0 + r) * DIMC + d4);
        *(float4*)(T + r * KST + d4) = v;
    }
    __syncthreads();

    const int wmq = (wid & 1) * 16;
    const int wnq = (wid >> 1) * 16;

    uint32_t qa[8][4];
    #pragma unroll
    for (int ks = 0; ks < 8; ks++) {
        int kk = ks * 8;
        qa[ks][0] = __float_as_uint(T[(wmq + group    ) * KST + kk + tig    ]);
        qa[ks][1] = __float_as_uint(T[(wmq + group + 8) * KST + kk + tig    ]);
        qa[ks][2] = __float_as_uint(T[(wmq + group    ) * KST + kk + tig + 4]);
        qa[ks][3] = __float_as_uint(T[(wmq + group + 8) * KST + kk + tig + 4]);
    }
    __syncthreads();

    // QK^T over 8 chunks of 128 cols, register-prefetched
    float4 pk[4];
    #pragma unroll
    for (int p = 0; p < 4; p++) {
        int l = p * 512 + t;
        int j = l >> 4, d4 = (l & 15) * 4;
        pk[p] = *(const float4*)(Kt + base + (size_t)j * DIMC + d4);
    }

    for (int c = 0; c < 8; c++) {
        #pragma unroll
        for (int p = 0; p < 4; p++) {
            int l = p * 512 + t;
            int j = l >> 4, d4 = (l & 15) * 4;
            *(float4*)(T + j * KST + d4) = pk[p];
        }
        __syncthreads();
        if (c < 7) {
            #pragma unroll
            for (int p = 0; p < 4; p++) {
                int l = p * 512 + t;
                int j = l >> 4, d4 = (l & 15) * 4;
                pk[p] = *(const float4*)(Kt + base + (size_t)((c + 1) * 128 + j) * DIMC + d4);
            }
        }
        float acc[2][4] = {};
        #pragma unroll
        for (int ks = 0; ks < 8; ks++) {
            int kk = ks * 8;
            #pragma unroll
            for (int nf = 0; nf < 2; nf++) {
                int nb = wnq + nf * 8;
                uint32_t b0 = __float_as_uint(T[(nb + group) * KST + kk + tig    ]);
                uint32_t b1 = __float_as_uint(T[(nb + group) * KST + kk + tig + 4]);
                MMA_TF32(acc[nf], qa[ks][0], qa[ks][1], qa[ks][2], qa[ks][3], b0, b1);
            }
        }
        #pragma unroll
        for (int nf = 0; nf < 2; nf++) {
            int col = c * 128 + wnq + nf * 8 + tig * 2;
            *(float2*)(S + (size_t)(wmq + group    ) * SP + col) = make_float2(acc[nf][0], acc[nf][1]);
            *(float2*)(S + (size_t)(wmq + group + 8) * SP + col) = make_float2(acc[nf][2], acc[nf][3]);
        }
        __syncthreads();
    }

    // softmax
    {
        int r = t >> 4, g = t & 15;
        float* row = S + (size_t)r * SP;
        float m = -1e30f;
        #pragma unroll
        for (int p = 0; p < 16; p++) {
            float4 v = *(const float4*)(row + (p * 16 + g) * 4);
            m = fmaxf(m, fmaxf(fmaxf(v.x, v.y), fmaxf(v.z, v.w)));
        }
        #pragma unroll
        for (int o = 8; o; o >>= 1) m = fmaxf(m, __shfl_xor_sync(0xffffffffu, m, o, 16));
        float s = 0.f;
        #pragma unroll
        for (int p = 0; p < 16; p++) {
            float4 v = *(float4*)(row + (p * 16 + g) * 4);
            v.x = __expf(v.x - m); v.y = __expf(v.y - m);
            v.z = __expf(v.z - m); v.w = __expf(v.w - m);
            s += v.x + v.y + v.z + v.w;
            *(float4*)(row + (p * 16 + g) * 4) = v;
        }
        #pragma unroll
        for (int o = 8; o; o >>= 1) s += __shfl_xor_sync(0xffffffffu, s, o, 16);
        if (g == 0) sinv[r] = 1.f / s;
    }
    __syncthreads();

    // normalized attn store (coalesced float4)
    {
        const size_t abase = (((size_t)b * HH + h) * NN + iq0) * NN;
        #pragma unroll
        for (int p = 0; p < 16; p++) {
            int r  = p * 2 + (t >> 8);
            int c4 = (t & 255) * 4;
            float inv = sinv[r];
            float4 v = *(const float4*)(S + (size_t)r * SP + c4);
            v.x *= inv; v.y *= inv; v.z *= inv; v.w *= inv;
            *(float4*)(attn + abase + (size_t)r * NN + c4) = v;
        }
    }
}

// ---------------------------------------------------------------------------
// pv_gemm: O = attn @ V per (mtile, h, b). 256x64 tile, 512 threads,
// 16 warps (8m x 2n), warp tile 32x32, 3-stage cp.async.
// P staged raw, tf32-rounded at fragment read; V pre-rounded.
// ---------------------------------------------------------------------------
#define PV_SMEM ((3 * 256 * 20 + 3 * 16 * 72) * 4)   // 75264 B

__global__ __launch_bounds__(512) void pv_gemm(
    const float* __restrict__ P, const float* __restrict__ V,
    float* __restrict__ O)
{
    extern __shared__ float smp[];
    float* As = smp;                    // [3][256][20]
    float* Bs = smp + 3 * 5120;         // [3][16][72]

    const int t     = threadIdx.x;
    const int wid   = t >> 5, lane = t & 31;
    const int group = lane >> 2, tig = lane & 3;
    const int wm    = (wid & 7) * 32;
    const int wn    = (wid >> 3) * 32;
    const int m0    = blockIdx.x * 256;
    const int h     = blockIdx.y, b = blockIdx.z;

    const float* Pb = P + (((size_t)b * HH + h) * NN + m0) * NN;
    const float* Vb = V + (size_t)b * NN * DIMC + (size_t)h * DHD;
    float*       Ob = O + (size_t)b * NN * DIMC + (size_t)h * DHD;

    auto load_stage = [&](int s, int k0) {
        float* Ad = As + s * 5120;
        float* Bd = Bs + s * 1152;
        #pragma unroll
        for (int l = 0; l < 2; l++) {
            int c = l * 512 + t;
            int r = c >> 2, k4 = (c & 3) * 4;
            cp16(Ad + r * 20 + k4, Pb + (size_t)r * NN + k0 + k4);
        }
        if (t < 256) {
            int kr = t >> 4, n4 = (t & 15) * 4;
            cp16(Bd + kr * 72 + n4, Vb + (size_t)(k0 + kr) * DIMC + n4);
        }
    };

    float acc[2][4][4] = {};

    load_stage(0, 0);  cp_commit();
    load_stage(1, 16); cp_commit();

    int s = 0;
    for (int k0 = 0; k0 < NN; k0 += 16) {
        cp_wait1();
        __syncthreads();
        int s2 = (s >= 1) ? s - 1 : s + 2;
        if (k0 + 32 < NN) load_stage(s2, k0 + 32);
        cp_commit();

        const float* Ac = As + s * 5120;
        const float* Bc = Bs + s * 1152;
        #pragma unroll
        for (int ks = 0; ks < 2; ks++) {
            int kk = ks * 8;
            uint32_t a[2][4];
            #pragma unroll
            for (int mf = 0; mf < 2; mf++) {
                int mb = wm + mf * 16;
                a[mf][0] = __float_as_uint(tf32r(Ac[(mb + group    ) * 20 + kk + tig    ]));
                a[mf][1] = __float_as_uint(tf32r(Ac[(mb + group + 8) * 20 + kk + tig    ]));
                a[mf][2] = __float_as_uint(tf32r(Ac[(mb + group    ) * 20 + kk + tig + 4]));
                a[mf][3] = __float_as_uint(tf32r(Ac[(mb + group + 8) * 20 + kk + tig + 4]));
            }
            #pragma unroll
            for (int nf = 0; nf < 4; nf++) {
                int nb = wn + nf * 8;
                uint32_t b0 = __float_as_uint(Bc[(kk + tig    ) * 72 + nb + group]);
                uint32_t b1 = __float_as_uint(Bc[(kk + tig + 4) * 72 + nb + group]);
                #pragma unroll
                for (int mf = 0; mf < 2; mf++)
                    MMA_TF32(acc[mf][nf], a[mf][0], a[mf][1], a[mf][2], a[mf][3], b0, b1);
            }
        }
        s = (s == 2) ? 0 : s + 1;
        __syncthreads();
    }

    #pragma unroll
    for (int mf = 0; mf < 2; mf++) {
        #pragma unroll
        for (int nf = 0; nf < 4; nf++) {
            int row = m0 + wm + mf * 16 + group;
            int col = wn + nf * 8 + tig * 2;
            *(float2*)(Ob + (size_t)row       * DIMC + col) =
                make_float2(tf32r(acc[mf][nf][0]), tf32r(acc[mf][nf][1]));
            *(float2*)(Ob + (size_t)(row + 8) * DIMC + col) =
                make_float2(tf32r(acc[mf][nf][2]), tf32r(acc[mf][nf][3]));
        }
    }
}

// ---------------------------------------------------------------------------
extern "C" void kernel_launch(void* const* d_in, const int* in_sizes, int n_in,
                              void* d_out, int out_size)
{
    const float* x  = (const float*)d_in[0];
    const float* Wq = (const float*)d_in[1];
    const float* Wk = (const float*)d_in[2];
    const float* Wv = (const float*)d_in[3];
    const float* Wo = (const float*)d_in[4];
    const float* bo = (const float*)d_in[5];

    float* out  = (float*)d_out;
    float* attn = out + (size_t)BB * NN * DIMC;

    float *Qp, *Kp, *Vp, *Op, *Xr, *Wqr, *Wkr, *Wvr, *Wor;
    cudaGetSymbolAddress((void**)&Qp,  g_Q);
    cudaGetSymbolAddress((void**)&Kp,  g_K);
    cudaGetSymbolAddress((void**)&Vp,  g_V);
    cudaGetSymbolAddress((void**)&Op,  g_O);
    cudaGetSymbolAddress((void**)&Xr,  g_Xr);
    cudaGetSymbolAddress((void**)&Wqr, g_Wqr);
    cudaGetSymbolAddress((void**)&Wkr, g_Wkr);
    cudaGetSymbolAddress((void**)&Wvr, g_Wvr);
    cudaGetSymbolAddress((void**)&Wor, g_Wor);

    cudaFuncSetAttribute(gemm_qkv, cudaFuncAttributeMaxDynamicSharedMemorySize, GEMM_SMEM);
    cudaFuncSetAttribute(gemm_out, cudaFuncAttributeMaxDynamicSharedMemorySize, GEMM_SMEM);
    cudaFuncSetAttribute(attn_qk,  cudaFuncAttributeMaxDynamicSharedMemorySize, ATTN_SMEM);
    cudaFuncSetAttribute(pv_gemm,  cudaFuncAttributeMaxDynamicSharedMemorySize, PV_SMEM);

    round_all<<<8192, 256>>>(x, Wq, Wk, Wv, Wo, Xr, Wqr, Wkr, Wvr, Wor);

    dim3 gQKV(8, 32, 3);
    gemm_qkv<<<gQKV, 512, GEMM_SMEM>>>(Xr, Wqr, Wkr, Wvr, Qp, Kp, Vp);

    dim3 gQK(NN / 32, HH, BB);
    attn_qk<<<gQK, 512, ATTN_SMEM>>>(Qp, Kp, attn);

    dim3 gPV(NN / 256, HH, BB);
    pv_gemm<<<gPV, 512, PV_SMEM>>>(attn, Vp, Op);

    dim3 gOut(8, 32);
    gemm_out<<<gOut, 512, GEMM_SMEM>>>(Op, Wor, out, bo);
}

// round 7
// speedup vs baseline: 1.5849x; 1.0321x over previous
#include <cuda_runtime.h>
#include <cstdint>
#include <cstddef>

#define BB   4
#define NN   1024
#define DIMC 1024
#define HH   16
#define DHD  64

// Scratch (no cudaMalloc allowed)
__device__ float g_Q[(size_t)BB * NN * DIMC];
__device__ float g_K[(size_t)BB * NN * DIMC];
__device__ float g_V[(size_t)BB * NN * DIMC];
__device__ float g_O[(size_t)BB * NN * DIMC];
__device__ float g_Xr[(size_t)BB * NN * DIMC];
__device__ float g_Wqr[(size_t)DIMC * HH * DHD];
__device__ float g_Wkr[(size_t)DIMC * HH * DHD];
__device__ float g_Wvr[(size_t)DIMC * HH * DHD];
__device__ float g_Wor[(size_t)HH * DHD * DIMC];

__device__ __forceinline__ float tf32r(float x) {
    uint32_t u;
    asm("cvt.rna.tf32.f32 %0, %1;" : "=r"(u) : "f"(x));
    return __uint_as_float(u);
}

__device__ __forceinline__ void cp16(float* smem, const float* gmem) {
    uint32_t s = (uint32_t)__cvta_generic_to_shared(smem);
    asm volatile("cp.async.cg.shared.global [%0], [%1], 16;" :: "r"(s), "l"(gmem));
}
__device__ __forceinline__ void cp_commit() { asm volatile("cp.async.commit_group;"); }
__device__ __forceinline__ void cp_wait0()  { asm volatile("cp.async.wait_group 0;"); }
__device__ __forceinline__ void cp_wait1()  { asm volatile("cp.async.wait_group 1;"); }

#define MMA_TF32(d, a0, a1, a2, a3, b0, b1)                                 \
    asm volatile(                                                           \
        "mma.sync.aligned.m16n8k8.row.col.f32.tf32.tf32.f32 "               \
        "{%0,%1,%2,%3}, {%4,%5,%6,%7}, {%8,%9}, {%0,%1,%2,%3};"             \
        : "+f"(d[0]), "+f"(d[1]), "+f"(d[2]), "+f"(d[3])                    \
        : "r"(a0), "r"(a1), "r"(a2), "r"(a3), "r"(b0), "r"(b1))

// ---------------------------------------------------------------------------
// Pre-round x and all weights to tf32 (rna) once.
// ---------------------------------------------------------------------------
__global__ __launch_bounds__(256) void round_all(
    const float* __restrict__ x,
    const float* __restrict__ Wq, const float* __restrict__ Wk,
    const float* __restrict__ Wv, const float* __restrict__ Wo,
    float* __restrict__ xr,
    float* __restrict__ wqr, float* __restrict__ wkr,
    float* __restrict__ wvr, float* __restrict__ wor)
{
    int i = blockIdx.x * blockDim.x + threadIdx.x;   // float4 index, 2M total
    const float* src; float* dst; int off;
    if (i < (1 << 20)) { src = x; dst = xr; off = i; }
    else {
        int j = i - (1 << 20);
        int w = j >> 18; off = j & ((1 << 18) - 1);
        src = (w == 0) ? Wq : (w == 1) ? Wk : (w == 2) ? Wv : Wo;
        dst = (w == 0) ? wqr : (w == 1) ? wkr : (w == 2) ? wvr : wor;
    }
    float4 v = ((const float4*)src)[off];
    v.x = tf32r(v.x); v.y = tf32r(v.y); v.z = tf32r(v.z); v.w = tf32r(v.w);
    ((float4*)dst)[off] = v;
}

// ---------------------------------------------------------------------------
// tf32 GEMM, 512 threads, 128x128 tile, BK=16, 3-stage cp.async pipeline.
// 16 warps (4m x 4n), warp tile 32x32.
// ---------------------------------------------------------------------------
#define GEMM_SMEM ((3 * 128 * 20 + 3 * 16 * 136) * 4)   // 56832 B

template<bool ROUND_OUT>
__device__ __forceinline__ void gemm_body(
    const float* __restrict__ A, const float* __restrict__ Bm,
    float* __restrict__ C, const float* __restrict__ bias,
    float outScale, int K, int Nc)
{
    extern __shared__ float smg[];
    float* As = smg;                    // [3][128][20]
    float* Bs = smg + 3 * 2560;         // [3][16][136]

    const int t     = threadIdx.x;
    const int wid   = t >> 5, lane = t & 31;
    const int group = lane >> 2, tig = lane & 3;
    const int wm    = (wid & 3) * 32;
    const int wn    = (wid >> 2) * 32;
    const int m0    = blockIdx.y * 128;
    const int n0    = blockIdx.x * 128;

    auto load_stage = [&](int s, int k0) {
        float* Ad = As + s * 2560;
        float* Bd = Bs + s * 2176;
        {
            int r = t >> 2, k4 = (t & 3) * 4;
            cp16(Ad + r * 20 + k4, A + (size_t)(m0 + r) * K + k0 + k4);
        }
        {
            int kr = t >> 5, b4 = (t & 31) * 4;
            cp16(Bd + kr * 136 + (b4 ^ ((kr & 12) << 1)),
                 Bm + (size_t)(k0 + kr) * Nc + n0 + b4);
        }
    };

    float acc[2][4][4] = {};

    load_stage(0, 0);  cp_commit();
    load_stage(1, 16); cp_commit();

    int s = 0;
    for (int k0 = 0; k0 < K; k0 += 16) {
        cp_wait1();
        __syncthreads();
        int s2 = (s >= 1) ? s - 1 : s + 2;
        if (k0 + 32 < K) load_stage(s2, k0 + 32);
        cp_commit();

        const float* Ac = As + s * 2560;
        const float* Bc = Bs + s * 2176;
        #pragma unroll
        for (int ks = 0; ks < 2; ks++) {
            int kk = ks * 8;
            int s0 = kk << 1;
            int s1 = ((kk + 4) & 12) << 1;
            uint32_t a[2][4];
            #pragma unroll
            for (int mf = 0; mf < 2; mf++) {
                int mb = wm + mf * 16;
                a[mf][0] = __float_as_uint(Ac[(mb + group    ) * 20 + kk + tig    ]);
                a[mf][1] = __float_as_uint(Ac[(mb + group + 8) * 20 + kk + tig    ]);
                a[mf][2] = __float_as_uint(Ac[(mb + group    ) * 20 + kk + tig + 4]);
                a[mf][3] = __float_as_uint(Ac[(mb + group + 8) * 20 + kk + tig + 4]);
            }
            #pragma unroll
            for (int nf = 0; nf < 4; nf++) {
                int nb = wn + nf * 8;
                uint32_t b0 = __float_as_uint(Bc[(kk + tig    ) * 136 + ((nb + group) ^ s0)]);
                uint32_t b1 = __float_as_uint(Bc[(kk + tig + 4) * 136 + ((nb + group) ^ s1)]);
                #pragma unroll
                for (int mf = 0; mf < 2; mf++)
                    MMA_TF32(acc[mf][nf], a[mf][0], a[mf][1], a[mf][2], a[mf][3], b0, b1);
            }
        }
        s = (s == 2) ? 0 : s + 1;
        __syncthreads();
    }

    #pragma unroll
    for (int mf = 0; mf < 2; mf++) {
        #pragma unroll
        for (int nf = 0; nf < 4; nf++) {
            int row = m0 + wm + mf * 16 + group;
            int col = n0 + wn + nf * 8 + tig * 2;
            float v0, v1, v2, v3;
            if (ROUND_OUT) {
                v0 = tf32r(acc[mf][nf][0] * outScale);
                v1 = tf32r(acc[mf][nf][1] * outScale);
                v2 = tf32r(acc[mf][nf][2] * outScale);
                v3 = tf32r(acc[mf][nf][3] * outScale);
            } else {
                float bx = bias[col], by = bias[col + 1];
                v0 = acc[mf][nf][0] + bx; v1 = acc[mf][nf][1] + by;
                v2 = acc[mf][nf][2] + bx; v3 = acc[mf][nf][3] + by;
            }
            *(float2*)(C + (size_t)row       * Nc + col) = make_float2(v0, v1);
            *(float2*)(C + (size_t)(row + 8) * Nc + col) = make_float2(v2, v3);
        }
    }
}

__global__ __launch_bounds__(512) void gemm_qkv(
    const float* __restrict__ x,
    const float* __restrict__ Wq, const float* __restrict__ Wk,
    const float* __restrict__ Wv,
    float* __restrict__ Qo, float* __restrict__ Ko, float* __restrict__ Vo)
{
    const float* W = (blockIdx.z == 0) ? Wq : (blockIdx.z == 1) ? Wk : Wv;
    float*       C = (blockIdx.z == 0) ? Qo : (blockIdx.z == 1) ? Ko : Vo;
    float scale    = (blockIdx.z == 0) ? 0.125f : 1.0f;
    gemm_body<true>(x, W, C, nullptr, scale, DIMC, HH * DHD);
}

__global__ __launch_bounds__(512) void gemm_out(
    const float* __restrict__ A, const float* __restrict__ W,
    float* __restrict__ C, const float* __restrict__ bias)
{
    gemm_body<false>(A, W, C, bias, 1.0f, DIMC, DIMC);
}

// ---------------------------------------------------------------------------
// qk_gemm: S_raw[b,h,i,j] = Qs[i,:] . K[j,:]  (Q pre-scaled+rounded).
// 128x128 output tile per block, K-dim = 64 (one smem load, no k-loop).
// 512 threads, 16 warps (4m x 4n), warp tile 32x32. Raw fp32 scores out.
// ---------------------------------------------------------------------------
#define QK_SMEM (2 * 128 * 68 * 4)   // 69632 B

__global__ __launch_bounds__(512) void qk_gemm(
    const float* __restrict__ Q, const float* __restrict__ Kt,
    float* __restrict__ Sraw)
{
    extern __shared__ float smq[];
    float* Qs = smq;             // [128][68]
    float* Ks = smq + 128 * 68;  // [128][68]

    const int t     = threadIdx.x;
    const int wid   = t >> 5, lane = t & 31;
    const int group = lane >> 2, tig = lane & 3;
    const int wm    = (wid & 3) * 32;
    const int wn    = (wid >> 2) * 32;
    const int n0    = blockIdx.x * 128;
    const int m0    = blockIdx.y * 128;
    const int b     = blockIdx.z >> 4, h = blockIdx.z & 15;
    const size_t base = (size_t)b * NN * DIMC + (size_t)h * DHD;

    #pragma unroll
    for (int p = 0; p < 4; p++) {
        int l = p * 512 + t;
        int r = l >> 4, d4 = (l & 15) * 4;
        cp16(Qs + r * 68 + d4, Q  + base + (size_t)(m0 + r) * DIMC + d4);
        cp16(Ks + r * 68 + d4, Kt + base + (size_t)(n0 + r) * DIMC + d4);
    }
    cp_commit();
    cp_wait0();
    __syncthreads();

    float acc[2][4][4] = {};
    #pragma unroll
    for (int ks = 0; ks < 8; ks++) {
        int kk = ks * 8;
        uint32_t a[2][4];
        #pragma unroll
        for (int mf = 0; mf < 2; mf++) {
            int mb = wm + mf * 16;
            a[mf][0] = __float_as_uint(Qs[(mb + group    ) * 68 + kk + tig    ]);
            a[mf][1] = __float_as_uint(Qs[(mb + group + 8) * 68 + kk + tig    ]);
            a[mf][2] = __float_as_uint(Qs[(mb + group    ) * 68 + kk + tig + 4]);
            a[mf][3] = __float_as_uint(Qs[(mb + group + 8) * 68 + kk + tig + 4]);
        }
        #pragma unroll
        for (int nf = 0; nf < 4; nf++) {
            int nb = wn + nf * 8;
            uint32_t b0 = __float_as_uint(Ks[(nb + group) * 68 + kk + tig    ]);
            uint32_t b1 = __float_as_uint(Ks[(nb + group) * 68 + kk + tig + 4]);
            #pragma unroll
            for (int mf = 0; mf < 2; mf++)
                MMA_TF32(acc[mf][nf], a[mf][0], a[mf][1], a[mf][2], a[mf][3], b0, b1);
        }
    }

    float* Sb = Sraw + (((size_t)b * HH + h) * NN + m0) * NN + n0;
    #pragma unroll
    for (int mf = 0; mf < 2; mf++) {
        #pragma unroll
        for (int nf = 0; nf < 4; nf++) {
            int row = wm + mf * 16 + group;
            int col = wn + nf * 8 + tig * 2;
            *(float2*)(Sb + (size_t)row       * NN + col) =
                make_float2(acc[mf][nf][0], acc[mf][nf][1]);
            *(float2*)(Sb + (size_t)(row + 8) * NN + col) =
                make_float2(acc[mf][nf][2], acc[mf][nf][3]);
        }
    }
}

// ---------------------------------------------------------------------------
// softmax_rows: in-place row softmax over S (65536 rows of 1024).
// One warp per row; row held entirely in 32 registers (8 x float4/lane).
// ---------------------------------------------------------------------------
__global__ __launch_bounds__(256) void softmax_rows(float* __restrict__ S)
{
    const int row  = blockIdx.x * 8 + (threadIdx.x >> 5);
    const int lane = threadIdx.x & 31;
    float* r = S + (size_t)row * NN;

    float4 v[8];
    #pragma unroll
    for (int i = 0; i < 8; i++) v[i] = *(const float4*)(r + (i * 32 + lane) * 4);

    float m = -1e30f;
    #pragma unroll
    for (int i = 0; i < 8; i++)
        m = fmaxf(m, fmaxf(fmaxf(v[i].x, v[i].y), fmaxf(v[i].z, v[i].w)));
    #pragma unroll
    for (int o = 16; o; o >>= 1) m = fmaxf(m, __shfl_xor_sync(0xffffffffu, m, o));

    float s = 0.f;
    #pragma unroll
    for (int i = 0; i < 8; i++) {
        v[i].x = __expf(v[i].x - m); v[i].y = __expf(v[i].y - m);
        v[i].z = __expf(v[i].z - m); v[i].w = __expf(v[i].w - m);
        s += v[i].x + v[i].y + v[i].z + v[i].w;
    }
    #pragma unroll
    for (int o = 16; o; o >>= 1) s += __shfl_xor_sync(0xffffffffu, s, o);
    float inv = 1.f / s;

    #pragma unroll
    for (int i = 0; i < 8; i++) {
        v[i].x *= inv; v[i].y *= inv; v[i].z *= inv; v[i].w *= inv;
        *(float4*)(r + (i * 32 + lane) * 4) = v[i];
    }
}

// ---------------------------------------------------------------------------
// pv_gemm: O = attn @ V per (mtile, h, b). 256x64 tile, 512 threads,
// 16 warps (8m x 2n), warp tile 32x32, 3-stage cp.async.
// P staged raw, tf32-rounded at fragment read; V pre-rounded.
// ---------------------------------------------------------------------------
#define PV_SMEM ((3 * 256 * 20 + 3 * 16 * 72) * 4)   // 75264 B

__global__ __launch_bounds__(512) void pv_gemm(
    const float* __restrict__ P, const float* __restrict__ V,
    float* __restrict__ O)
{
    extern __shared__ float smp[];
    float* As = smp;                    // [3][256][20]
    float* Bs = smp + 3 * 5120;         // [3][16][72]

    const int t     = threadIdx.x;
    const int wid   = t >> 5, lane = t & 31;
    const int group = lane >> 2, tig = lane & 3;
    const int wm    = (wid & 7) * 32;
    const int wn    = (wid >> 3) * 32;
    const int m0    = blockIdx.x * 256;
    const int h     = blockIdx.y, b = blockIdx.z;

    const float* Pb = P + (((size_t)b * HH + h) * NN + m0) * NN;
    const float* Vb = V + (size_t)b * NN * DIMC + (size_t)h * DHD;
    float*       Ob = O + (size_t)b * NN * DIMC + (size_t)h * DHD;

    auto load_stage = [&](int s, int k0) {
        float* Ad = As + s * 5120;
        float* Bd = Bs + s * 1152;
        #pragma unroll
        for (int l = 0; l < 2; l++) {
            int c = l * 512 + t;
            int r = c >> 2, k4 = (c & 3) * 4;
            cp16(Ad + r * 20 + k4, Pb + (size_t)r * NN + k0 + k4);
        }
        if (t < 256) {
            int kr = t >> 4, n4 = (t & 15) * 4;
            cp16(Bd + kr * 72 + n4, Vb + (size_t)(k0 + kr) * DIMC + n4);
        }
    };

    float acc[2][4][4] = {};

    load_stage(0, 0);  cp_commit();
    load_stage(1, 16); cp_commit();

    int s = 0;
    for (int k0 = 0; k0 < NN; k0 += 16) {
        cp_wait1();
        __syncthreads();
        int s2 = (s >= 1) ? s - 1 : s + 2;
        if (k0 + 32 < NN) load_stage(s2, k0 + 32);
        cp_commit();

        const float* Ac = As + s * 5120;
        const float* Bc = Bs + s * 1152;
        #pragma unroll
        for (int ks = 0; ks < 2; ks++) {
            int kk = ks * 8;
            uint32_t a[2][4];
            #pragma unroll
            for (int mf = 0; mf < 2; mf++) {
                int mb = wm + mf * 16;
                a[mf][0] = __float_as_uint(tf32r(Ac[(mb + group    ) * 20 + kk + tig    ]));
                a[mf][1] = __float_as_uint(tf32r(Ac[(mb + group + 8) * 20 + kk + tig    ]));
                a[mf][2] = __float_as_uint(tf32r(Ac[(mb + group    ) * 20 + kk + tig + 4]));
                a[mf][3] = __float_as_uint(tf32r(Ac[(mb + group + 8) * 20 + kk + tig + 4]));
            }
            #pragma unroll
            for (int nf = 0; nf < 4; nf++) {
                int nb = wn + nf * 8;
                uint32_t b0 = __float_as_uint(Bc[(kk + tig    ) * 72 + nb + group]);
                uint32_t b1 = __float_as_uint(Bc[(kk + tig + 4) * 72 + nb + group]);
                #pragma unroll
                for (int mf = 0; mf < 2; mf++)
                    MMA_TF32(acc[mf][nf], a[mf][0], a[mf][1], a[mf][2], a[mf][3], b0, b1);
            }
        }
        s = (s == 2) ? 0 : s + 1;
        __syncthreads();
    }

    #pragma unroll
    for (int mf = 0; mf < 2; mf++) {
        #pragma unroll
        for (int nf = 0; nf < 4; nf++) {
            int row = m0 + wm + mf * 16 + group;
            int col = wn + nf * 8 + tig * 2;
            *(float2*)(Ob + (size_t)row       * DIMC + col) =
                make_float2(tf32r(acc[mf][nf][0]), tf32r(acc[mf][nf][1]));
            *(float2*)(Ob + (size_t)(row + 8) * DIMC + col) =
                make_float2(tf32r(acc[mf][nf][2]), tf32r(acc[mf][nf][3]));
        }
    }
}

// ---------------------------------------------------------------------------
extern "C" void kernel_launch(void* const* d_in, const int* in_sizes, int n_in,
                              void* d_out, int out_size)
{
    const float* x  = (const float*)d_in[0];
    const float* Wq = (const float*)d_in[1];
    const float* Wk = (const float*)d_in[2];
    const float* Wv = (const float*)d_in[3];
    const float* Wo = (const float*)d_in[4];
    const float* bo = (const float*)d_in[5];

    float* out  = (float*)d_out;
    float* attn = out + (size_t)BB * NN * DIMC;

    float *Qp, *Kp, *Vp, *Op, *Xr, *Wqr, *Wkr, *Wvr, *Wor;
    cudaGetSymbolAddress((void**)&Qp,  g_Q);
    cudaGetSymbolAddress((void**)&Kp,  g_K);
    cudaGetSymbolAddress((void**)&Vp,  g_V);
    cudaGetSymbolAddress((void**)&Op,  g_O);
    cudaGetSymbolAddress((void**)&Xr,  g_Xr);
    cudaGetSymbolAddress((void**)&Wqr, g_Wqr);
    cudaGetSymbolAddress((void**)&Wkr, g_Wkr);
    cudaGetSymbolAddress((void**)&Wvr, g_Wvr);
    cudaGetSymbolAddress((void**)&Wor, g_Wor);

    cudaFuncSetAttribute(gemm_qkv, cudaFuncAttributeMaxDynamicSharedMemorySize, GEMM_SMEM);
    cudaFuncSetAttribute(gemm_out, cudaFuncAttributeMaxDynamicSharedMemorySize, GEMM_SMEM);
    cudaFuncSetAttribute(qk_gemm,  cudaFuncAttributeMaxDynamicSharedMemorySize, QK_SMEM);
    cudaFuncSetAttribute(pv_gemm,  cudaFuncAttributeMaxDynamicSharedMemorySize, PV_SMEM);

    round_all<<<8192, 256>>>(x, Wq, Wk, Wv, Wo, Xr, Wqr, Wkr, Wvr, Wor);

    dim3 gQKV(8, 32, 3);
    gemm_qkv<<<gQKV, 512, GEMM_SMEM>>>(Xr, Wqr, Wkr, Wvr, Qp, Kp, Vp);

    dim3 gQK(8, 8, BB * HH);   // (n-tiles, m-tiles, b*16+h)
    qk_gemm<<<gQK, 512, QK_SMEM>>>(Qp, Kp, attn);

    softmax_rows<<<BB * HH * NN / 8, 256>>>(attn);

    dim3 gPV(NN / 256, HH, BB);
    pv_gemm<<<gPV, 512, PV_SMEM>>>(attn, Vp, Op);

    dim3 gOut(8, 32);
    gemm_out<<<gOut, 512, GEMM_SMEM>>>(Op, Wor, out, bo);
}

// round 8
// speedup vs baseline: 1.6157x; 1.0195x over previous
#include <cuda_runtime.h>
#include <cstdint>
#include <cstddef>

#define BB   4
#define NN   1024
#define DIMC 1024
#define HH   16
#define DHD  64

// Scratch (no cudaMalloc allowed)
__device__ float g_Q[(size_t)BB * NN * DIMC];
__device__ float g_K[(size_t)BB * NN * DIMC];
__device__ float g_V[(size_t)BB * NN * DIMC];
__device__ float g_O[(size_t)BB * NN * DIMC];
__device__ float g_Xr[(size_t)BB * NN * DIMC];
__device__ float g_Wqr[(size_t)DIMC * HH * DHD];
__device__ float g_Wkr[(size_t)DIMC * HH * DHD];
__device__ float g_Wvr[(size_t)DIMC * HH * DHD];
__device__ float g_Wor[(size_t)HH * DHD * DIMC];
__device__ float g_psum[(size_t)BB * HH * NN * 8];   // per-row per-ntile exp sums
__device__ float g_inv[(size_t)BB * HH * NN];        // 1/rowsum

__device__ __forceinline__ float tf32r(float x) {
    uint32_t u;
    asm("cvt.rna.tf32.f32 %0, %1;" : "=r"(u) : "f"(x));
    return __uint_as_float(u);
}

__device__ __forceinline__ void cp16(float* smem, const float* gmem) {
    uint32_t s = (uint32_t)__cvta_generic_to_shared(smem);
    asm volatile("cp.async.cg.shared.global [%0], [%1], 16;" :: "r"(s), "l"(gmem));
}
__device__ __forceinline__ void cp_commit() { asm volatile("cp.async.commit_group;"); }
__device__ __forceinline__ void cp_wait0()  { asm volatile("cp.async.wait_group 0;"); }
__device__ __forceinline__ void cp_wait1()  { asm volatile("cp.async.wait_group 1;"); }

#define MMA_TF32(d, a0, a1, a2, a3, b0, b1)                                 \
    asm volatile(                                                           \
        "mma.sync.aligned.m16n8k8.row.col.f32.tf32.tf32.f32 "               \
        "{%0,%1,%2,%3}, {%4,%5,%6,%7}, {%8,%9}, {%0,%1,%2,%3};"             \
        : "+f"(d[0]), "+f"(d[1]), "+f"(d[2]), "+f"(d[3])                    \
        : "r"(a0), "r"(a1), "r"(a2), "r"(a3), "r"(b0), "r"(b1))

// ---------------------------------------------------------------------------
// Pre-round x and all weights to tf32 (rna) once.
// ---------------------------------------------------------------------------
__global__ __launch_bounds__(256) void round_all(
    const float* __restrict__ x,
    const float* __restrict__ Wq, const float* __restrict__ Wk,
    const float* __restrict__ Wv, const float* __restrict__ Wo,
    float* __restrict__ xr,
    float* __restrict__ wqr, float* __restrict__ wkr,
    float* __restrict__ wvr, float* __restrict__ wor)
{
    int i = blockIdx.x * blockDim.x + threadIdx.x;   // float4 index, 2M total
    const float* src; float* dst; int off;
    if (i < (1 << 20)) { src = x; dst = xr; off = i; }
    else {
        int j = i - (1 << 20);
        int w = j >> 18; off = j & ((1 << 18) - 1);
        src = (w == 0) ? Wq : (w == 1) ? Wk : (w == 2) ? Wv : Wo;
        dst = (w == 0) ? wqr : (w == 1) ? wkr : (w == 2) ? wvr : wor;
    }
    float4 v = ((const float4*)src)[off];
    v.x = tf32r(v.x); v.y = tf32r(v.y); v.z = tf32r(v.z); v.w = tf32r(v.w);
    ((float4*)dst)[off] = v;
}

// ---------------------------------------------------------------------------
// tf32 GEMM, 512 threads, 128x128 tile, BK=16, 3-stage cp.async pipeline.
// ---------------------------------------------------------------------------
#define GEMM_SMEM ((3 * 128 * 20 + 3 * 16 * 136) * 4)   // 56832 B

template<bool ROUND_OUT>
__device__ __forceinline__ void gemm_body(
    const float* __restrict__ A, const float* __restrict__ Bm,
    float* __restrict__ C, const float* __restrict__ bias,
    float outScale, int K, int Nc)
{
    extern __shared__ float smg[];
    float* As = smg;                    // [3][128][20]
    float* Bs = smg + 3 * 2560;         // [3][16][136]

    const int t     = threadIdx.x;
    const int wid   = t >> 5, lane = t & 31;
    const int group = lane >> 2, tig = lane & 3;
    const int wm    = (wid & 3) * 32;
    const int wn    = (wid >> 2) * 32;
    const int m0    = blockIdx.y * 128;
    const int n0    = blockIdx.x * 128;

    auto load_stage = [&](int s, int k0) {
        float* Ad = As + s * 2560;
        float* Bd = Bs + s * 2176;
        {
            int r = t >> 2, k4 = (t & 3) * 4;
            cp16(Ad + r * 20 + k4, A + (size_t)(m0 + r) * K + k0 + k4);
        }
        {
            int kr = t >> 5, b4 = (t & 31) * 4;
            cp16(Bd + kr * 136 + (b4 ^ ((kr & 12) << 1)),
                 Bm + (size_t)(k0 + kr) * Nc + n0 + b4);
        }
    };

    float acc[2][4][4] = {};

    load_stage(0, 0);  cp_commit();
    load_stage(1, 16); cp_commit();

    int s = 0;
    for (int k0 = 0; k0 < K; k0 += 16) {
        cp_wait1();
        __syncthreads();
        int s2 = (s >= 1) ? s - 1 : s + 2;
        if (k0 + 32 < K) load_stage(s2, k0 + 32);
        cp_commit();

        const float* Ac = As + s * 2560;
        const float* Bc = Bs + s * 2176;
        #pragma unroll
        for (int ks = 0; ks < 2; ks++) {
            int kk = ks * 8;
            int s0 = kk << 1;
            int s1 = ((kk + 4) & 12) << 1;
            uint32_t a[2][4];
            #pragma unroll
            for (int mf = 0; mf < 2; mf++) {
                int mb = wm + mf * 16;
                a[mf][0] = __float_as_uint(Ac[(mb + group    ) * 20 + kk + tig    ]);
                a[mf][1] = __float_as_uint(Ac[(mb + group + 8) * 20 + kk + tig    ]);
                a[mf][2] = __float_as_uint(Ac[(mb + group    ) * 20 + kk + tig + 4]);
                a[mf][3] = __float_as_uint(Ac[(mb + group + 8) * 20 + kk + tig + 4]);
            }
            #pragma unroll
            for (int nf = 0; nf < 4; nf++) {
                int nb = wn + nf * 8;
                uint32_t b0 = __float_as_uint(Bc[(kk + tig    ) * 136 + ((nb + group) ^ s0)]);
                uint32_t b1 = __float_as_uint(Bc[(kk + tig + 4) * 136 + ((nb + group) ^ s1)]);
                #pragma unroll
                for (int mf = 0; mf < 2; mf++)
                    MMA_TF32(acc[mf][nf], a[mf][0], a[mf][1], a[mf][2], a[mf][3], b0, b1);
            }
        }
        s = (s == 2) ? 0 : s + 1;
        __syncthreads();
    }

    #pragma unroll
    for (int mf = 0; mf < 2; mf++) {
        #pragma unroll
        for (int nf = 0; nf < 4; nf++) {
            int row = m0 + wm + mf * 16 + group;
            int col = n0 + wn + nf * 8 + tig * 2;
            float v0, v1, v2, v3;
            if (ROUND_OUT) {
                v0 = tf32r(acc[mf][nf][0] * outScale);
                v1 = tf32r(acc[mf][nf][1] * outScale);
                v2 = tf32r(acc[mf][nf][2] * outScale);
                v3 = tf32r(acc[mf][nf][3] * outScale);
            } else {
                float bx = bias[col], by = bias[col + 1];
                v0 = acc[mf][nf][0] + bx; v1 = acc[mf][nf][1] + by;
                v2 = acc[mf][nf][2] + bx; v3 = acc[mf][nf][3] + by;
            }
            *(float2*)(C + (size_t)row       * Nc + col) = make_float2(v0, v1);
            *(float2*)(C + (size_t)(row + 8) * Nc + col) = make_float2(v2, v3);
        }
    }
}

__global__ __launch_bounds__(512) void gemm_qkv(
    const float* __restrict__ x,
    const float* __restrict__ Wq, const float* __restrict__ Wk,
    const float* __restrict__ Wv,
    float* __restrict__ Qo, float* __restrict__ Ko, float* __restrict__ Vo)
{
    const float* W = (blockIdx.z == 0) ? Wq : (blockIdx.z == 1) ? Wk : Wv;
    float*       C = (blockIdx.z == 0) ? Qo : (blockIdx.z == 1) ? Ko : Vo;
    float scale    = (blockIdx.z == 0) ? 0.125f : 1.0f;
    gemm_body<true>(x, W, C, nullptr, scale, DIMC, HH * DHD);
}

__global__ __launch_bounds__(512) void gemm_out(
    const float* __restrict__ A, const float* __restrict__ W,
    float* __restrict__ C, const float* __restrict__ bias)
{
    gemm_body<false>(A, W, C, bias, 1.0f, DIMC, DIMC);
}

// ---------------------------------------------------------------------------
// qk_gemm: E[b,h,i,j] = exp(Qs[i,:].K[j,:]) (unnormalized), plus per-tile
// row sums -> psum[row][ntile]. 128x128 tile, 512 threads, 16 warps.
// No max subtraction: scores are O(10), exp cannot overflow fp32.
// ---------------------------------------------------------------------------
#define QK_SMEM (2 * 128 * 68 * 4)   // 69632 B

__global__ __launch_bounds__(512) void qk_gemm(
    const float* __restrict__ Q, const float* __restrict__ Kt,
    float* __restrict__ Sexp, float* __restrict__ psum)
{
    extern __shared__ float smq[];
    float* Qs = smq;             // [128][68]
    float* Ks = smq + 128 * 68;  // [128][68]
    __shared__ float rowpart[128][4];

    const int t     = threadIdx.x;
    const int wid   = t >> 5, lane = t & 31;
    const int group = lane >> 2, tig = lane & 3;
    const int wm    = (wid & 3) * 32;
    const int wn    = (wid >> 2) * 32;
    const int n0    = blockIdx.x * 128;
    const int m0    = blockIdx.y * 128;
    const int b     = blockIdx.z >> 4, h = blockIdx.z & 15;
    const size_t base = (size_t)b * NN * DIMC + (size_t)h * DHD;

    #pragma unroll
    for (int p = 0; p < 4; p++) {
        int l = p * 512 + t;
        int r = l >> 4, d4 = (l & 15) * 4;
        cp16(Qs + r * 68 + d4, Q  + base + (size_t)(m0 + r) * DIMC + d4);
        cp16(Ks + r * 68 + d4, Kt + base + (size_t)(n0 + r) * DIMC + d4);
    }
    cp_commit();
    cp_wait0();
    __syncthreads();

    float acc[2][4][4] = {};
    #pragma unroll
    for (int ks = 0; ks < 8; ks++) {
        int kk = ks * 8;
        uint32_t a[2][4];
        #pragma unroll
        for (int mf = 0; mf < 2; mf++) {
            int mb = wm + mf * 16;
            a[mf][0] = __float_as_uint(Qs[(mb + group    ) * 68 + kk + tig    ]);
            a[mf][1] = __float_as_uint(Qs[(mb + group + 8) * 68 + kk + tig    ]);
            a[mf][2] = __float_as_uint(Qs[(mb + group    ) * 68 + kk + tig + 4]);
            a[mf][3] = __float_as_uint(Qs[(mb + group + 8) * 68 + kk + tig + 4]);
        }
        #pragma unroll
        for (int nf = 0; nf < 4; nf++) {
            int nb = wn + nf * 8;
            uint32_t b0 = __float_as_uint(Ks[(nb + group) * 68 + kk + tig    ]);
            uint32_t b1 = __float_as_uint(Ks[(nb + group) * 68 + kk + tig + 4]);
            #pragma unroll
            for (int mf = 0; mf < 2; mf++)
                MMA_TF32(acc[mf][nf], a[mf][0], a[mf][1], a[mf][2], a[mf][3], b0, b1);
        }
    }

    // exp + store + per-row partial sums
    float* Sb = Sexp + (((size_t)b * HH + h) * NN + m0) * NN + n0;
    #pragma unroll
    for (int mf = 0; mf < 2; mf++) {
        float sra = 0.f, srb = 0.f;
        #pragma unroll
        for (int nf = 0; nf < 4; nf++) {
            float e0 = __expf(acc[mf][nf][0]);
            float e1 = __expf(acc[mf][nf][1]);
            float e2 = __expf(acc[mf][nf][2]);
            float e3 = __expf(acc[mf][nf][3]);
            sra += e0 + e1;
            srb += e2 + e3;
            int row = wm + mf * 16 + group;
            int col = wn + nf * 8 + tig * 2;
            *(float2*)(Sb + (size_t)row       * NN + col) = make_float2(e0, e1);
            *(float2*)(Sb + (size_t)(row + 8) * NN + col) = make_float2(e2, e3);
        }
        // reduce across tig (lane bits 0,1)
        sra += __shfl_xor_sync(0xffffffffu, sra, 1);
        sra += __shfl_xor_sync(0xffffffffu, sra, 2);
        srb += __shfl_xor_sync(0xffffffffu, srb, 1);
        srb += __shfl_xor_sync(0xffffffffu, srb, 2);
        if (tig == 0) {
            rowpart[wm + mf * 16 + group    ][wid >> 2] = sra;
            rowpart[wm + mf * 16 + group + 8][wid >> 2] = srb;
        }
    }
    __syncthreads();
    if (t < 128) {
        float ssum = rowpart[t][0] + rowpart[t][1] + rowpart[t][2] + rowpart[t][3];
        psum[(((size_t)b * HH + h) * NN + m0 + t) * 8 + blockIdx.x] = ssum;
    }
}

// ---------------------------------------------------------------------------
// inv_sums: inv[row] = 1 / sum over 8 tile partials.
// ---------------------------------------------------------------------------
__global__ __launch_bounds__(256) void inv_sums(
    const float* __restrict__ psum, float* __restrict__ inv)
{
    int r = blockIdx.x * 256 + threadIdx.x;
    const float4* p = (const float4*)(psum + (size_t)r * 8);
    float4 a = p[0], c = p[1];
    inv[r] = 1.f / (a.x + a.y + a.z + a.w + c.x + c.y + c.z + c.w);
}

// ---------------------------------------------------------------------------
// pv_fused: O = (E * inv) @ V ; also writes normalized attn in-place from
// staged smem. 256x64 tile, 512 threads, 16 warps (8m x 2n), 3-stage cp.async.
// ---------------------------------------------------------------------------
#define PV_SMEM ((3 * 256 * 20 + 3 * 16 * 72) * 4)   // 75264 B

__global__ __launch_bounds__(512) void pv_fused(
    float* __restrict__ P, const float* __restrict__ V,
    const float* __restrict__ inv, float* __restrict__ O)
{
    extern __shared__ float smp[];
    float* As = smp;                    // [3][256][20]
    float* Bs = smp + 3 * 5120;         // [3][16][72]

    const int t     = threadIdx.x;
    const int wid   = t >> 5, lane = t & 31;
    const int group = lane >> 2, tig = lane & 3;
    const int wm    = (wid & 7) * 32;
    const int wn    = (wid >> 3) * 32;
    const int m0    = blockIdx.x * 256;
    const int h     = blockIdx.y, b = blockIdx.z;

    const size_t rowbase = ((size_t)b * HH + h) * NN + m0;
    float*       Pb = P + rowbase * NN;
    const float* Vb = V + (size_t)b * NN * DIMC + (size_t)h * DHD;
    float*       Ob = O + (size_t)b * NN * DIMC + (size_t)h * DHD;

    // inverse row sums for this thread's fragment rows and staged rows
    float fi[4];
    #pragma unroll
    for (int mf = 0; mf < 2; mf++) {
        fi[mf * 2    ] = inv[rowbase + wm + mf * 16 + group    ];
        fi[mf * 2 + 1] = inv[rowbase + wm + mf * 16 + group + 8];
    }
    float wi[2];
    #pragma unroll
    for (int l = 0; l < 2; l++) wi[l] = inv[rowbase + ((l * 512 + t) >> 2)];

    auto load_stage = [&](int s, int k0) {
        float* Ad = As + s * 5120;
        float* Bd = Bs + s * 1152;
        #pragma unroll
        for (int l = 0; l < 2; l++) {
            int c = l * 512 + t;
            int r = c >> 2, k4 = (c & 3) * 4;
            cp16(Ad + r * 20 + k4, Pb + (size_t)r * NN + k0 + k4);
        }
        if (t < 256) {
            int kr = t >> 4, n4 = (t & 15) * 4;
            cp16(Bd + kr * 72 + n4, Vb + (size_t)(k0 + kr) * DIMC + n4);
        }
    };

    float acc[2][4][4] = {};

    load_stage(0, 0);  cp_commit();
    load_stage(1, 16); cp_commit();

    int s = 0;
    for (int k0 = 0; k0 < NN; k0 += 16) {
        cp_wait1();
        __syncthreads();
        int s2 = (s >= 1) ? s - 1 : s + 2;
        if (k0 + 32 < NN) load_stage(s2, k0 + 32);
        cp_commit();

        const float* Ac = As + s * 5120;
        const float* Bc = Bs + s * 1152;

        // write normalized attn chunk back to gmem (from staged raw expS)
        #pragma unroll
        for (int l = 0; l < 2; l++) {
            int c = l * 512 + t;
            int r = c >> 2, k4 = (c & 3) * 4;
            const float* src = Ac + r * 20 + k4;
            float4 v;
            v.x = src[0] * wi[l]; v.y = src[1] * wi[l];
            v.z = src[2] * wi[l]; v.w = src[3] * wi[l];
            *(float4*)(Pb + (size_t)r * NN + k0 + k4) = v;
        }

        #pragma unroll
        for (int ks = 0; ks < 2; ks++) {
            int kk = ks * 8;
            uint32_t a[2][4];
            #pragma unroll
            for (int mf = 0; mf < 2; mf++) {
                int mb = wm + mf * 16;
                a[mf][0] = __float_as_uint(tf32r(Ac[(mb + group    ) * 20 + kk + tig    ] * fi[mf * 2    ]));
                a[mf][1] = __float_as_uint(tf32r(Ac[(mb + group + 8) * 20 + kk + tig    ] * fi[mf * 2 + 1]));
                a[mf][2] = __float_as_uint(tf32r(Ac[(mb + group    ) * 20 + kk + tig + 4] * fi[mf * 2    ]));
                a[mf][3] = __float_as_uint(tf32r(Ac[(mb + group + 8) * 20 + kk + tig + 4] * fi[mf * 2 + 1]));
            }
            #pragma unroll
            for (int nf = 0; nf < 4; nf++) {
                int nb = wn + nf * 8;
                uint32_t b0 = __float_as_uint(Bc[(kk + tig    ) * 72 + nb + group]);
                uint32_t b1 = __float_as_uint(Bc[(kk + tig + 4) * 72 + nb + group]);
                #pragma unroll
                for (int mf = 0; mf < 2; mf++)
                    MMA_TF32(acc[mf][nf], a[mf][0], a[mf][1], a[mf][2], a[mf][3], b0, b1);
            }
        }
        s = (s == 2) ? 0 : s + 1;
        __syncthreads();
    }

    #pragma unroll
    for (int mf = 0; mf < 2; mf++) {
        #pragma unroll
        for (int nf = 0; nf < 4; nf++) {
            int row = m0 + wm + mf * 16 + group;
            int col = wn + nf * 8 + tig * 2;
            *(float2*)(Ob + (size_t)row       * DIMC + col) =
                make_float2(tf32r(acc[mf][nf][0]), tf32r(acc[mf][nf][1]));
            *(float2*)(Ob + (size_t)(row + 8) * DIMC + col) =
                make_float2(tf32r(acc[mf][nf][2]), tf32r(acc[mf][nf][3]));
        }
    }
}

// ---------------------------------------------------------------------------
extern "C" void kernel_launch(void* const* d_in, const int* in_sizes, int n_in,
                              void* d_out, int out_size)
{
    const float* x  = (const float*)d_in[0];
    const float* Wq = (const float*)d_in[1];
    const float* Wk = (const float*)d_in[2];
    const float* Wv = (const float*)d_in[3];
    const float* Wo = (const float*)d_in[4];
    const float* bo = (const float*)d_in[5];

    float* out  = (float*)d_out;
    float* attn = out + (size_t)BB * NN * DIMC;

    float *Qp, *Kp, *Vp, *Op, *Xr, *Wqr, *Wkr, *Wvr, *Wor, *Ps, *Iv;
    cudaGetSymbolAddress((void**)&Qp,  g_Q);
    cudaGetSymbolAddress((void**)&Kp,  g_K);
    cudaGetSymbolAddress((void**)&Vp,  g_V);
    cudaGetSymbolAddress((void**)&Op,  g_O);
    cudaGetSymbolAddress((void**)&Xr,  g_Xr);
    cudaGetSymbolAddress((void**)&Wqr, g_Wqr);
    cudaGetSymbolAddress((void**)&Wkr, g_Wkr);
    cudaGetSymbolAddress((void**)&Wvr, g_Wvr);
    cudaGetSymbolAddress((void**)&Wor, g_Wor);
    cudaGetSymbolAddress((void**)&Ps,  g_psum);
    cudaGetSymbolAddress((void**)&Iv,  g_inv);

    cudaFuncSetAttribute(gemm_qkv, cudaFuncAttributeMaxDynamicSharedMemorySize, GEMM_SMEM);
    cudaFuncSetAttribute(gemm_out, cudaFuncAttributeMaxDynamicSharedMemorySize, GEMM_SMEM);
    cudaFuncSetAttribute(qk_gemm,  cudaFuncAttributeMaxDynamicSharedMemorySize, QK_SMEM);
    cudaFuncSetAttribute(pv_fused, cudaFuncAttributeMaxDynamicSharedMemorySize, PV_SMEM);

    round_all<<<8192, 256>>>(x, Wq, Wk, Wv, Wo, Xr, Wqr, Wkr, Wvr, Wor);

    dim3 gQKV(8, 32, 3);
    gemm_qkv<<<gQKV, 512, GEMM_SMEM>>>(Xr, Wqr, Wkr, Wvr, Qp, Kp, Vp);

    dim3 gQK(8, 8, BB * HH);
    qk_gemm<<<gQK, 512, QK_SMEM>>>(Qp, Kp, attn, Ps);

    inv_sums<<<BB * HH * NN / 256, 256>>>(Ps, Iv);

    dim3 gPV(NN / 256, HH, BB);
    pv_fused<<<gPV, 512, PV_SMEM>>>(attn, Vp, Iv, Op);

    dim3 gOut(8, 32);
    gemm_out<<<gOut, 512, GEMM_SMEM>>>(Op, Wor, out, bo);
}